// round 6
// baseline (speedup 1.0000x reference)
#include <cuda_runtime.h>
#include <math.h>

#define Bn 4
#define Nn 4096
#define En 16384

#define ROWB 144                   // smem row stride in bytes (36 floats)
#define STAGEB (128 * ROWB)        // bytes per operand per stage = 18432
#define NSTG 2
#define BOFF (NSTG * STAGEB)       // B operand base offset
#define SMEM_BYTES (2 * NSTG * STAGEB)  // 73728

// ---------------------------------------------------------------------------
// Static device scratch
// ---------------------------------------------------------------------------
__device__ __align__(16) float g_AG[(size_t)Bn * Nn * 512];    // [a_in | a_out]
__device__ __align__(16) float g_RZ[(size_t)Bn * Nn * 512];    // [r*h | z]
__device__ __align__(16) float g_h[(size_t)Bn * Nn * 256];
__device__ __align__(16) float g_ann[(size_t)Bn * Nn * 64];
__device__ __align__(16) float g_Wt[16 * 256 * 256];
__device__ __align__(16) float g_Wrz[512 * 768];
__device__ __align__(16) float g_Wh[256 * 768];
__device__ __align__(16) float g_brz[512];
__device__ float g_nodeval[Bn * Nn];
__device__ int g_cnt[32];
__device__ int g_cur[32];
__device__ int g_off[33];
__device__ int g_eidx[Bn * En];

// ---------------------------------------------------------------------------
// Helpers
// ---------------------------------------------------------------------------
__device__ __forceinline__ unsigned f2tf(float x) {
    unsigned r;
    asm("cvt.rna.tf32.f32 %0, %1;" : "=r"(r) : "f"(x));
    return r;
}
__device__ __forceinline__ float roundtf(float x) { return __uint_as_float(f2tf(x)); }

__device__ __forceinline__ void mma1688(float* c, const unsigned* a, const unsigned* b) {
    asm volatile(
        "mma.sync.aligned.m16n8k8.row.col.f32.tf32.tf32.f32 "
        "{%0,%1,%2,%3}, {%4,%5,%6,%7}, {%8,%9}, {%0,%1,%2,%3};"
        : "+f"(c[0]), "+f"(c[1]), "+f"(c[2]), "+f"(c[3])
        : "r"(a[0]), "r"(a[1]), "r"(a[2]), "r"(a[3]), "r"(b[0]), "r"(b[1]));
}

__device__ __forceinline__ void redadd2(float* p, float x, float y) {
    asm volatile("red.global.add.v2.f32 [%0], {%1,%2};"
                 :: "l"(p), "f"(x), "f"(y) : "memory");
}

__device__ __forceinline__ void cpasync16(unsigned saddr, const float* gptr) {
    asm volatile("cp.async.cg.shared.global [%0], [%1], 16;" :: "r"(saddr), "l"(gptr));
}
__device__ __forceinline__ void cpcommit() { asm volatile("cp.async.commit_group;"); }
__device__ __forceinline__ void cpwait1() { asm volatile("cp.async.wait_group 1;"); }

__device__ __forceinline__ void ldmx4(unsigned& r0, unsigned& r1, unsigned& r2, unsigned& r3,
                                      unsigned addr) {
    asm volatile("ldmatrix.sync.aligned.m8n8.x4.shared.b16 {%0,%1,%2,%3}, [%4];"
                 : "=r"(r0), "=r"(r1), "=r"(r2), "=r"(r3) : "r"(addr));
}

// ---------------------------------------------------------------------------
// MMA consume of one 128x128x32 stage via ldmatrix.
// aLane/bLane are per-thread byte offsets (warp tile + lane pattern baked in).
//   A frag (m16k8, b32): ldm.x4 over 16 rows x 16 b16: lanes 0-15 -> rows,
//   lanes 16-31 -> +16B; regs = (a0,a1,a2,a3) of mma.
//   B frag: lanes 0-7 n0-7 k+0; 8-15 n0-7 k+16B; 16-23 n8-15 k+0; 24-31 n8-15 +16B;
//   regs = (b0 tile0, b1 tile0, b0 tile1, b1 tile1).
// ---------------------------------------------------------------------------
__device__ __forceinline__ void consume_tile(unsigned smBase, int stage,
                                             unsigned aLane, unsigned bLane,
                                             float acc[4][4][4])
{
    const unsigned sA = smBase + stage * STAGEB + aLane;
    const unsigned sB = smBase + stage * STAGEB + bLane;
#pragma unroll
    for (int ks = 0; ks < 4; ks++) {
        unsigned bf[4][2];
#pragma unroll
        for (int p = 0; p < 2; p++) {
            unsigned r0, r1, r2, r3;
            ldmx4(r0, r1, r2, r3, sB + p * (16 * ROWB) + ks * 32);
            bf[2 * p][0] = r0; bf[2 * p][1] = r1;
            bf[2 * p + 1][0] = r2; bf[2 * p + 1][1] = r3;
        }
#pragma unroll
        for (int mt = 0; mt < 4; mt++) {
            unsigned a[4];
            ldmx4(a[0], a[1], a[2], a[3], sA + mt * (16 * ROWB) + ks * 32);
#pragma unroll
            for (int nt = 0; nt < 4; nt++)
                mma1688(acc[mt][nt], a, bf[nt]);
        }
    }
}

// ---------------------------------------------------------------------------
// Edge sort by (batch, etype) -> 32 bins
// ---------------------------------------------------------------------------
__global__ void zero_sort_k() {
    int i = threadIdx.x;
    if (i < 32) { g_cnt[i] = 0; g_cur[i] = 0; }
}
__global__ void hist_k(const int* __restrict__ et) {
    int e = blockIdx.x * 256 + threadIdx.x;
    atomicAdd(&g_cnt[(e >> 14) * 8 + et[e]], 1);
}
__global__ void scan_k() {
    int i = threadIdx.x;
    int s = g_cnt[i];
#pragma unroll
    for (int d = 1; d < 32; d <<= 1) {
        int u = __shfl_up_sync(0xffffffffu, s, d);
        if (i >= d) s += u;
    }
    g_off[i + 1] = s;
    if (i == 0) g_off[0] = 0;
}
__global__ void build_k(const int* __restrict__ et) {
    int e = blockIdx.x * 256 + threadIdx.x;
    int bin = (e >> 14) * 8 + et[e];
    int pos = g_off[bin] + atomicAdd(&g_cur[bin], 1);
    g_eidx[pos] = e;
}

// ---------------------------------------------------------------------------
// Gather-GEMM + fused scatter (tile 128x128, BK=32, cp.async double-buffer)
// ---------------------------------------------------------------------------
__global__ void __launch_bounds__(256, 2) gather_gemm_k(
    const int* __restrict__ src, const int* __restrict__ dst,
    const float* __restrict__ eb, int K)
{
    int zz = blockIdx.z;
    int grp = zz >> 1, dir = zz & 1;
    int b = grp >> 3, t = grp & 7;
    int off = g_off[grp];
    int cnt = g_off[grp + 1] - off;
    int m0 = blockIdx.x * 128;
    if (m0 >= cnt) return;

    extern __shared__ float sm[];
    unsigned smBase = (unsigned)__cvta_generic_to_shared(sm);

    const int tid = threadIdx.x;
    const int wid = tid >> 5, lane = tid & 31;
    const int g = lane >> 2, tg = lane & 3;
    const int wm = (wid >> 2) * 64;
    const int wn = (wid & 3) * 32;
    const int n0 = blockIdx.y * 128;

    const int* gidx = dir ? src : dst;
    const int* sidx = dir ? dst : src;
    const float* W = g_Wt + (size_t)(t + dir * 8) * 65536;
    const float* bias = eb + (size_t)(t + dir * 8) * 256;
    const float* hb = g_h + (size_t)b * Nn * 256;
    float* agb = g_AG + (size_t)b * Nn * 512 + (dir ? 0 : 256);

    // fill setup: 2 threads per row (half rows of 16 floats)
    const int frow = tid >> 1, fhalf = tid & 1;
    int mg = m0 + frow;
    if (mg >= cnt) mg = cnt - 1;
    const float* rowA = hb + (size_t)gidx[g_eidx[off + mg]] * 256 + fhalf * 16;
    const float* rowB = W + (size_t)(n0 + frow) * 256 + fhalf * 16;
    const unsigned fillA = smBase + frow * ROWB + fhalf * 64;
    const unsigned fillB = smBase + BOFF + frow * ROWB + fhalf * 64;

    const unsigned aLane = smBase + (wm + (lane & 15)) * ROWB + (lane >> 4) * 16;
    const unsigned bLane = smBase + BOFF +
        (wn + (lane & 7) + ((lane >> 4) & 1) * 8) * ROWB + ((lane >> 3) & 1) * 16;

    float acc[4][4][4];
#pragma unroll
    for (int mt = 0; mt < 4; mt++)
#pragma unroll
        for (int nt = 0; nt < 4; nt++)
#pragma unroll
            for (int c = 0; c < 4; c++) acc[mt][nt][c] = 0.f;

    const int KT = K >> 5;
    // prologue: stage 0
    {
        const float* a = rowA;
        const float* bb = rowB;
#pragma unroll
        for (int j = 0; j < 4; j++) {
            cpasync16(fillA + j * 16, a + j * 4);
            cpasync16(fillB + j * 16, bb + j * 4);
        }
        cpcommit();
    }
    for (int kt = 0; kt < KT; kt++) {
        if (kt + 1 < KT) {
            unsigned so = ((kt + 1) & 1) * STAGEB;
            const float* a = rowA + (kt + 1) * 32;
            const float* bb = rowB + (kt + 1) * 32;
#pragma unroll
            for (int j = 0; j < 4; j++) {
                cpasync16(fillA + so + j * 16, a + j * 4);
                cpasync16(fillB + so + j * 16, bb + j * 4);
            }
        }
        cpcommit();
        cpwait1();
        __syncthreads();
        consume_tile(smBase, kt & 1, aLane - smBase + smBase, aLane - smBase, acc);
        // NOTE: consume_tile takes offsets relative to smBase:
        __syncthreads();
    }

    // epilogue: add per-edge-type bias, scatter-add into AG
#pragma unroll
    for (int mt = 0; mt < 4; mt++) {
        int mrow = m0 + wm + mt * 16 + g;
#pragma unroll
        for (int nt = 0; nt < 4; nt++) {
            int colg = n0 + wn + nt * 8 + 2 * tg;
            float b0 = bias[colg], b1 = bias[colg + 1];
            if (mrow < cnt) {
                int e = g_eidx[off + mrow];
                redadd2(agb + (size_t)sidx[e] * 512 + colg,
                        acc[mt][nt][0] + b0, acc[mt][nt][1] + b1);
            }
            if (mrow + 8 < cnt) {
                int e = g_eidx[off + mrow + 8];
                redadd2(agb + (size_t)sidx[e] * 512 + colg,
                        acc[mt][nt][2] + b0, acc[mt][nt][3] + b1);
            }
        }
    }
}

// ---------------------------------------------------------------------------
// Split-A GEMM: A logical row = [ A (512 cols) | A2 (256 cols) ], K = 768.
// ACT 1 (rz): col<256 -> RZ[.,col] = round(sigmoid(v)*h) ; col>=256 -> RZ = sigmoid(v)
// ACT 2 (hh): h = round((1-z)h + z*tanh(v))
// ---------------------------------------------------------------------------
template <int ACT>
__device__ __forceinline__ void split_gemm(const float* __restrict__ A, int lda,
                                           const float* __restrict__ A2, int lda2,
                                           const float* __restrict__ B, int ldb,
                                           float* __restrict__ C, int ldc,
                                           const float* __restrict__ bias,
                                           const float* __restrict__ Zp,
                                           float* __restrict__ Hp)
{
    extern __shared__ float sm[];
    unsigned smBase = (unsigned)__cvta_generic_to_shared(sm);

    const int tid = threadIdx.x;
    const int wid = tid >> 5, lane = tid & 31;
    const int g = lane >> 2, tg = lane & 3;
    const int wm = (wid >> 2) * 64;
    const int wn = (wid & 3) * 32;
    const int m0 = blockIdx.x * 128;
    const int n0 = blockIdx.y * 128;

    const int frow = tid >> 1, fhalf = tid & 1;
    const float* rowB = B + (size_t)(n0 + frow) * ldb + fhalf * 16;
    const unsigned fillA = smBase + frow * ROWB + fhalf * 64;
    const unsigned fillB = smBase + BOFF + frow * ROWB + fhalf * 64;

    const unsigned aLane = (wm + (lane & 15)) * ROWB + (lane >> 4) * 16;
    const unsigned bLane = BOFF +
        (wn + (lane & 7) + ((lane >> 4) & 1) * 8) * ROWB + ((lane >> 3) & 1) * 16;

    float acc[4][4][4];
#pragma unroll
    for (int mt = 0; mt < 4; mt++)
#pragma unroll
        for (int nt = 0; nt < 4; nt++)
#pragma unroll
            for (int c = 0; c < 4; c++) acc[mt][nt][c] = 0.f;

    const int KT = 24;  // K = 768, BK = 32

    auto asrc = [&](int kt) -> const float* {
        int k = kt * 32;
        return (k < 512) ? A + (size_t)(m0 + frow) * lda + k + fhalf * 16
                         : A2 + (size_t)(m0 + frow) * lda2 + (k - 512) + fhalf * 16;
    };

    {
        const float* a = asrc(0);
        const float* bb = rowB;
#pragma unroll
        for (int j = 0; j < 4; j++) {
            cpasync16(fillA + j * 16, a + j * 4);
            cpasync16(fillB + j * 16, bb + j * 4);
        }
        cpcommit();
    }
    for (int kt = 0; kt < KT; kt++) {
        if (kt + 1 < KT) {
            unsigned so = ((kt + 1) & 1) * STAGEB;
            const float* a = asrc(kt + 1);
            const float* bb = rowB + (kt + 1) * 32;
#pragma unroll
            for (int j = 0; j < 4; j++) {
                cpasync16(fillA + so + j * 16, a + j * 4);
                cpasync16(fillB + so + j * 16, bb + j * 4);
            }
        }
        cpcommit();
        cpwait1();
        __syncthreads();
        consume_tile(smBase, kt & 1, aLane, bLane, acc);
        __syncthreads();
    }

#pragma unroll
    for (int mt = 0; mt < 4; mt++) {
#pragma unroll
        for (int nt = 0; nt < 4; nt++) {
            int row = m0 + wm + mt * 16 + g;
            int col = n0 + wn + nt * 8 + 2 * tg;
            float b0 = bias[col], b1 = bias[col + 1];
            float v0 = acc[mt][nt][0] + b0, v1 = acc[mt][nt][1] + b1;
            float v2 = acc[mt][nt][2] + b0, v3 = acc[mt][nt][3] + b1;
            if (ACT == 1) {
                float s0 = 1.f / (1.f + expf(-v0)), s1 = 1.f / (1.f + expf(-v1));
                float s2 = 1.f / (1.f + expf(-v2)), s3 = 1.f / (1.f + expf(-v3));
                float* p0 = C + (size_t)row * ldc + col;
                float* p1 = C + (size_t)(row + 8) * ldc + col;
                if (col < 256) {
                    const float* h0 = Zp + (size_t)row * 256 + col;
                    const float* h1 = Zp + (size_t)(row + 8) * 256 + col;
                    *(float2*)p0 = make_float2(roundtf(s0 * h0[0]), roundtf(s1 * h0[1]));
                    *(float2*)p1 = make_float2(roundtf(s2 * h1[0]), roundtf(s3 * h1[1]));
                } else {
                    *(float2*)p0 = make_float2(s0, s1);
                    *(float2*)p1 = make_float2(s2, s3);
                }
            } else {
                float z0 = Zp[(size_t)row * 512 + col], z1 = Zp[(size_t)row * 512 + col + 1];
                float z2 = Zp[(size_t)(row + 8) * 512 + col], z3 = Zp[(size_t)(row + 8) * 512 + col + 1];
                float* hp0 = Hp + (size_t)row * 256 + col;
                float* hp1 = Hp + (size_t)(row + 8) * 256 + col;
                float h0 = hp0[0], h1 = hp0[1], h2 = hp1[0], h3 = hp1[1];
                *(float2*)hp0 = make_float2(roundtf((1.f - z0) * h0 + z0 * tanhf(v0)),
                                            roundtf((1.f - z1) * h1 + z1 * tanhf(v1)));
                *(float2*)hp1 = make_float2(roundtf((1.f - z2) * h2 + z2 * tanhf(v2)),
                                            roundtf((1.f - z3) * h3 + z3 * tanhf(v3)));
            }
        }
    }
}

__global__ void __launch_bounds__(256, 2) gemm_rz_k() {
    split_gemm<1>(g_AG, 512, g_h, 256, g_Wrz, 768, g_RZ, 512, g_brz, g_h, nullptr);
}
__global__ void __launch_bounds__(256, 2) gemm_hh_k(const float* __restrict__ bh) {
    split_gemm<2>(g_AG, 512, g_RZ, 512, g_Wh, 768, nullptr, 0, bh, g_RZ + 256, g_h);
}

// ---------------------------------------------------------------------------
// Setup kernels
// ---------------------------------------------------------------------------
__global__ void prep_Wt(const float* __restrict__ ee) {
    size_t i = (size_t)blockIdx.x * 256 + threadIdx.x;
    g_Wt[i] = roundtf(ee[i]);
}
__global__ void prep_Wrz(const float* __restrict__ Wr, const float* __restrict__ Wz,
                         const float* __restrict__ br, const float* __restrict__ bz) {
    int r = blockIdx.x;
    const float* s = (r < 256) ? (Wr + (size_t)r * 768) : (Wz + (size_t)(r - 256) * 768);
    for (int c = threadIdx.x; c < 768; c += blockDim.x)
        g_Wrz[(size_t)r * 768 + c] = roundtf(s[c]);
    if (threadIdx.x == 0) g_brz[r] = (r < 256) ? br[r] : bz[r - 256];
}
__global__ void prep_Wh(const float* __restrict__ Wh) {
    size_t i = (size_t)blockIdx.x * 256 + threadIdx.x;
    g_Wh[i] = roundtf(Wh[i]);
}
__global__ void init_h(const int* __restrict__ ann_id, const float* __restrict__ te) {
    int n = blockIdx.x;
    int i = threadIdx.x;
    int id = ann_id[n];
    float a = 0.f;
    if (i < 64 && id > 0) a = te[(size_t)(id - 1) * 64 + i];
    if (i < 64) g_ann[(size_t)n * 64 + i] = a;
    g_h[(size_t)n * 256 + i] = (i < 64) ? roundtf(a) : 0.f;
}
__global__ void prep_AG() {
    size_t i = (size_t)blockIdx.x * 256 + threadIdx.x;
    ((float4*)g_AG)[i] = make_float4(0.f, 0.f, 0.f, 0.f);
}

// ---------------------------------------------------------------------------
// Readout
// ---------------------------------------------------------------------------
__global__ void readout_k(const float* __restrict__ Wa, const float* __restrict__ ba,
                          const float* __restrict__ Wo, const float* __restrict__ bo) {
    int warp = (blockIdx.x * blockDim.x + threadIdx.x) >> 5;
    int lane = threadIdx.x & 31;
    const float* hrow = g_h + (size_t)warp * 256;
    const float* arow = g_ann + (size_t)warp * 64;
    float sa = 0.f, so = 0.f;
#pragma unroll
    for (int k = lane; k < 320; k += 32) {
        float v = (k < 256) ? hrow[k] : arow[k - 256];
        sa += v * Wa[k];
        so += v * Wo[k];
    }
#pragma unroll
    for (int off = 16; off; off >>= 1) {
        sa += __shfl_xor_sync(0xffffffffu, sa, off);
        so += __shfl_xor_sync(0xffffffffu, so, off);
    }
    if (lane == 0) {
        float atten = 1.f / (1.f + expf(-(sa + ba[0])));
        float ou = tanhf(so + bo[0]);
        g_nodeval[warp] = atten * ou;
    }
}

__global__ void finalize_k(float* __restrict__ out) {
    __shared__ float sh[256];
    int b = blockIdx.x;
    float s = 0.f;
    for (int i = threadIdx.x; i < Nn; i += 256) s += g_nodeval[(size_t)b * Nn + i];
    sh[threadIdx.x] = s;
    __syncthreads();
    for (int k = 128; k; k >>= 1) {
        if (threadIdx.x < k) sh[threadIdx.x] += sh[threadIdx.x + k];
        __syncthreads();
    }
    if (threadIdx.x == 0) out[b] = 1.f / (1.f + expf(-sh[0]));
}

// ---------------------------------------------------------------------------
// Launch
// ---------------------------------------------------------------------------
extern "C" void kernel_launch(void* const* d_in, const int* in_sizes, int n_in,
                              void* d_out, int out_size) {
    (void)in_sizes; (void)n_in; (void)out_size;
    const int* ann_id = (const int*)d_in[0];
    const int* src    = (const int*)d_in[1];
    const int* dst    = (const int*)d_in[2];
    const int* et     = (const int*)d_in[3];
    const float* ee   = (const float*)d_in[4];
    const float* eb   = (const float*)d_in[5];
    const float* te   = (const float*)d_in[6];
    const float* Wr   = (const float*)d_in[7];
    const float* br   = (const float*)d_in[8];
    const float* Wz   = (const float*)d_in[9];
    const float* bz   = (const float*)d_in[10];
    const float* Wh   = (const float*)d_in[11];
    const float* bh   = (const float*)d_in[12];
    const float* Wa   = (const float*)d_in[13];
    const float* ba   = (const float*)d_in[14];
    const float* Wo   = (const float*)d_in[15];
    const float* bo   = (const float*)d_in[16];
    float* out = (float*)d_out;

    cudaFuncSetAttribute(gather_gemm_k, cudaFuncAttributeMaxDynamicSharedMemorySize, SMEM_BYTES);
    cudaFuncSetAttribute(gemm_rz_k, cudaFuncAttributeMaxDynamicSharedMemorySize, SMEM_BYTES);
    cudaFuncSetAttribute(gemm_hh_k, cudaFuncAttributeMaxDynamicSharedMemorySize, SMEM_BYTES);

    prep_Wt<<<4096, 256>>>(ee);
    prep_Wrz<<<512, 256>>>(Wr, Wz, br, bz);
    prep_Wh<<<768, 256>>>(Wh);
    init_h<<<Bn * Nn, 256>>>(ann_id, te);

    zero_sort_k<<<1, 32>>>();
    hist_k<<<256, 256>>>(et);
    scan_k<<<1, 32>>>();
    build_k<<<256, 256>>>(et);

    for (int step = 0; step < 3; step++) {
        prep_AG<<<8192, 256>>>();
        gather_gemm_k<<<dim3(128, 2, 64), 256, SMEM_BYTES>>>(src, dst, eb,
                                                             step == 0 ? 64 : 256);
        gemm_rz_k<<<dim3(128, 4, 1), 256, SMEM_BYTES>>>();
        gemm_hh_k<<<dim3(128, 2, 1), 256, SMEM_BYTES>>>(bh);
    }

    readout_k<<<2048, 256>>>(Wa, ba, Wo, bo);
    finalize_k<<<4, 256>>>(out);
}

// round 7
// speedup vs baseline: 1.3323x; 1.3323x over previous
#include <cuda_runtime.h>
#include <cuda_bf16.h>
#include <math.h>

#define Bn 4
#define Nn 4096
#define En 16384

#define ROWB 80                     // smem row stride bytes (64B data + 16B pad)
#define OPB (128 * ROWB)            // bytes per operand per stage = 10240
#define STGB (2 * OPB)              // bytes per stage (A+B)
#define SMEM_BYTES (2 * STGB)       // 40960

// ---------------------------------------------------------------------------
// Static device scratch
// ---------------------------------------------------------------------------
__device__ __align__(16) float          g_AG [(size_t)Bn * Nn * 512];   // fp32 atomics [a_in|a_out]
__device__ __align__(16) unsigned short g_AGb[(size_t)Bn * Nn * 512];   // bf16 mirror
__device__ __align__(16) float          g_Z  [(size_t)Bn * Nn * 256];   // z (fp32)
__device__ __align__(16) unsigned short g_rhb[(size_t)Bn * Nn * 256];   // r*h (bf16)
__device__ __align__(16) float          g_h  [(size_t)Bn * Nn * 256];   // state fp32
__device__ __align__(16) unsigned short g_hb [(size_t)Bn * Nn * 256];   // state bf16
__device__ __align__(16) float          g_ann[(size_t)Bn * Nn * 64];
__device__ __align__(16) unsigned short g_Wtb [16 * 256 * 256];
__device__ __align__(16) unsigned short g_Wrzb[512 * 768];
__device__ __align__(16) unsigned short g_Whb [256 * 768];
__device__ __align__(16) float g_brz[512];
__device__ float g_nodeval[Bn * Nn];
__device__ int g_cnt[32], g_cur[32], g_off[33], g_toff[33];
__device__ int g_eidx[Bn * En];

// ---------------------------------------------------------------------------
// Helpers
// ---------------------------------------------------------------------------
__device__ __forceinline__ unsigned pkbf(float lo, float hi) {
    unsigned r;
    asm("cvt.rn.bf16x2.f32 %0, %1, %2;" : "=r"(r) : "f"(hi), "f"(lo));
    return r;
}
__device__ __forceinline__ unsigned short f2b(float x) {
    __nv_bfloat16 b = __float2bfloat16(x);
    return *(unsigned short*)&b;
}
__device__ __forceinline__ void mma_bf16(float* c, const unsigned* a, const unsigned* b) {
    asm volatile(
        "mma.sync.aligned.m16n8k16.row.col.f32.bf16.bf16.f32 "
        "{%0,%1,%2,%3}, {%4,%5,%6,%7}, {%8,%9}, {%0,%1,%2,%3};"
        : "+f"(c[0]), "+f"(c[1]), "+f"(c[2]), "+f"(c[3])
        : "r"(a[0]), "r"(a[1]), "r"(a[2]), "r"(a[3]), "r"(b[0]), "r"(b[1]));
}
__device__ __forceinline__ void ldmx4(unsigned& r0, unsigned& r1, unsigned& r2, unsigned& r3,
                                      unsigned addr) {
    asm volatile("ldmatrix.sync.aligned.m8n8.x4.shared.b16 {%0,%1,%2,%3}, [%4];"
                 : "=r"(r0), "=r"(r1), "=r"(r2), "=r"(r3) : "r"(addr));
}
__device__ __forceinline__ void redadd2(float* p, float x, float y) {
    asm volatile("red.global.add.v2.f32 [%0], {%1,%2};"
                 :: "l"(p), "f"(x), "f"(y) : "memory");
}

// Consume one 128x128x32(bf16) stage. All addresses absolute u32 shared.
__device__ __forceinline__ void consume_stage(unsigned baseA, unsigned baseB,
                                              int wm, int wn, int lane,
                                              float acc[4][4][4])
{
    const unsigned aOff = baseA + (unsigned)(wm + (lane & 15)) * ROWB + (lane >> 4) * 16;
    const unsigned bOff = baseB + (unsigned)(wn + (lane & 7) + ((lane >> 4) & 1) * 8) * ROWB
                        + ((lane >> 3) & 1) * 16;
#pragma unroll
    for (int ks = 0; ks < 2; ks++) {
        unsigned bf[4][2];
#pragma unroll
        for (int p = 0; p < 2; p++) {
            unsigned r0, r1, r2, r3;
            ldmx4(r0, r1, r2, r3, bOff + p * (16 * ROWB) + ks * 32);
            bf[2 * p][0] = r0; bf[2 * p][1] = r1;
            bf[2 * p + 1][0] = r2; bf[2 * p + 1][1] = r3;
        }
#pragma unroll
        for (int mt = 0; mt < 4; mt++) {
            unsigned a[4];
            ldmx4(a[0], a[1], a[2], a[3], aOff + mt * (16 * ROWB) + ks * 32);
#pragma unroll
            for (int nt = 0; nt < 4; nt++)
                mma_bf16(acc[mt][nt], a, bf[nt]);
        }
    }
}

// ---------------------------------------------------------------------------
// Edge sort by (batch, etype) -> 32 bins, plus tile-count prefix
// ---------------------------------------------------------------------------
__global__ void zero_sort_k() {
    int i = threadIdx.x;
    if (i < 32) { g_cnt[i] = 0; g_cur[i] = 0; }
}
__global__ void hist_k(const int* __restrict__ et) {
    int e = blockIdx.x * 256 + threadIdx.x;
    atomicAdd(&g_cnt[(e >> 14) * 8 + et[e]], 1);
}
__global__ void scan_k() {
    int i = threadIdx.x;
    int c = g_cnt[i];
    int s = c, t = (c + 127) >> 7;
#pragma unroll
    for (int d = 1; d < 32; d <<= 1) {
        int u1 = __shfl_up_sync(0xffffffffu, s, d);
        int u2 = __shfl_up_sync(0xffffffffu, t, d);
        if (i >= d) { s += u1; t += u2; }
    }
    g_off[i + 1] = s;
    g_toff[i + 1] = t;
    if (i == 0) { g_off[0] = 0; g_toff[0] = 0; }
}
__global__ void build_k(const int* __restrict__ et) {
    int e = blockIdx.x * 256 + threadIdx.x;
    int bin = (e >> 14) * 8 + et[e];
    int pos = g_off[bin] + atomicAdd(&g_cur[bin], 1);
    g_eidx[pos] = e;
}

// ---------------------------------------------------------------------------
// Gather-GEMM (bf16) + fused scatter.  grid (544, 2, 2): x=tile, y=n-tile, z=dir
// ---------------------------------------------------------------------------
__global__ void __launch_bounds__(256, 2) gather_gemm_k(
    const int* __restrict__ src, const int* __restrict__ dst,
    const float* __restrict__ eb, int KT)
{
    int tile = blockIdx.x;
    if (tile >= g_toff[32]) return;
    int grp = 0;
#pragma unroll 1
    while (tile >= g_toff[grp + 1]) grp++;
    const int m0 = (tile - g_toff[grp]) * 128;
    const int off = g_off[grp];
    const int cnt = g_off[grp + 1] - off;
    const int dir = blockIdx.z;
    const int b = grp >> 3, t = grp & 7;
    const int n0 = blockIdx.y * 128;

    extern __shared__ char sm[];
    const unsigned smBase = (unsigned)__cvta_generic_to_shared(sm);

    const int tid = threadIdx.x;
    const int lane = tid & 31, wid = tid >> 5;
    const int g = lane >> 2, tg = lane & 3;
    const int wm = (wid >> 2) * 64, wn = (wid & 3) * 32;

    const int* gidx = dir ? src : dst;
    const int* sidx = dir ? dst : src;
    const unsigned short* W = g_Wtb + (size_t)(t + dir * 8) * 65536;
    const float* bias = eb + (size_t)(t + dir * 8) * 256;
    const unsigned short* hb = g_hb + (size_t)b * Nn * 256;
    float* agb = g_AG + (size_t)b * Nn * 512 + (dir ? 0 : 256);

    // fill mapping: thread -> (row = tid&127, two 16B chunks selected by tid>>7)
    const int frow = tid & 127;
    const int fsub = (tid >> 7) * 2;          // uint4 index base within 64B tile-row
    int mg = m0 + frow; if (mg >= cnt) mg = cnt - 1;
    const uint4* rowA = (const uint4*)(hb + (size_t)gidx[g_eidx[off + mg]] * 256);
    const uint4* rowB = (const uint4*)(W + (size_t)(n0 + frow) * 256);
    const unsigned offA = (unsigned)frow * ROWB + fsub * 16;
    const unsigned offB = OPB + (unsigned)frow * ROWB + fsub * 16;

    float acc[4][4][4];
#pragma unroll
    for (int mt = 0; mt < 4; mt++)
#pragma unroll
        for (int nt = 0; nt < 4; nt++)
#pragma unroll
            for (int c = 0; c < 4; c++) acc[mt][nt][c] = 0.f;

    uint4 pa0 = rowA[fsub], pa1 = rowA[fsub + 1];
    uint4 pb0 = rowB[fsub], pb1 = rowB[fsub + 1];

    for (int kt = 0; kt < KT; kt++) {
        const unsigned sb = (kt & 1) * STGB;
        *(uint4*)(sm + sb + offA) = pa0;
        *(uint4*)(sm + sb + offA + 16) = pa1;
        *(uint4*)(sm + sb + offB) = pb0;
        *(uint4*)(sm + sb + offB + 16) = pb1;
        if (kt + 1 < KT) {
            int ni = (kt + 1) * 4 + fsub;
            pa0 = rowA[ni]; pa1 = rowA[ni + 1];
            pb0 = rowB[ni]; pb1 = rowB[ni + 1];
        }
        __syncthreads();
        consume_stage(smBase + sb, smBase + sb + OPB, wm, wn, lane, acc);
    }

    // epilogue: + edge-type bias, atomic scatter into AG
#pragma unroll
    for (int mt = 0; mt < 4; mt++) {
        int mrow = m0 + wm + mt * 16 + g;
#pragma unroll
        for (int nt = 0; nt < 4; nt++) {
            int colg = n0 + wn + nt * 8 + 2 * tg;
            float b0 = bias[colg], b1 = bias[colg + 1];
            if (mrow < cnt) {
                int e = g_eidx[off + mrow];
                redadd2(agb + (size_t)sidx[e] * 512 + colg,
                        acc[mt][nt][0] + b0, acc[mt][nt][1] + b1);
            }
            if (mrow + 8 < cnt) {
                int e = g_eidx[off + mrow + 8];
                redadd2(agb + (size_t)sidx[e] * 512 + colg,
                        acc[mt][nt][2] + b0, acc[mt][nt][3] + b1);
            }
        }
    }
}

// ---------------------------------------------------------------------------
// Split-A bf16 GEMM: A = [AGb (512 bf16) | region2 (256 bf16)], K tiles param.
// ACT 1 (rz): col<256 -> g_rhb = bf16(sigmoid(v)*h), col>=256 -> g_Z = sigmoid(v)
// ACT 2 (hh): h = (1-z)h + z*tanh(v)  -> g_h fp32 + g_hb bf16
// ---------------------------------------------------------------------------
template <int ACT>
__device__ __forceinline__ void split_gemm(const unsigned short* __restrict__ A2,
                                           const unsigned short* __restrict__ B, int ldb,
                                           const float* __restrict__ bias, int KT)
{
    extern __shared__ char sm[];
    const unsigned smBase = (unsigned)__cvta_generic_to_shared(sm);

    const int tid = threadIdx.x;
    const int lane = tid & 31, wid = tid >> 5;
    const int g = lane >> 2, tg = lane & 3;
    const int wm = (wid >> 2) * 64, wn = (wid & 3) * 32;
    const int m0 = blockIdx.x * 128;
    const int n0 = blockIdx.y * 128;

    const int frow = tid & 127;
    const int fsub = (tid >> 7) * 2;
    const uint4* rowA1 = (const uint4*)(g_AGb + (size_t)(m0 + frow) * 512);
    const uint4* rowA2 = (const uint4*)(A2 + (size_t)(m0 + frow) * 256);
    const uint4* rowB = (const uint4*)(B + (size_t)(n0 + frow) * ldb);
    const unsigned offA = (unsigned)frow * ROWB + fsub * 16;
    const unsigned offB = OPB + (unsigned)frow * ROWB + fsub * 16;

    float acc[4][4][4];
#pragma unroll
    for (int mt = 0; mt < 4; mt++)
#pragma unroll
        for (int nt = 0; nt < 4; nt++)
#pragma unroll
            for (int c = 0; c < 4; c++) acc[mt][nt][c] = 0.f;

    uint4 pa0 = rowA1[fsub], pa1 = rowA1[fsub + 1];
    uint4 pb0 = rowB[fsub], pb1 = rowB[fsub + 1];

    for (int kt = 0; kt < KT; kt++) {
        const unsigned sb = (kt & 1) * STGB;
        *(uint4*)(sm + sb + offA) = pa0;
        *(uint4*)(sm + sb + offA + 16) = pa1;
        *(uint4*)(sm + sb + offB) = pb0;
        *(uint4*)(sm + sb + offB + 16) = pb1;
        if (kt + 1 < KT) {
            int k2 = kt + 1;
            const uint4* ra = (k2 < 16) ? (rowA1 + k2 * 4 + fsub)
                                        : (rowA2 + (k2 - 16) * 4 + fsub);
            pa0 = ra[0]; pa1 = ra[1];
            int ni = k2 * 4 + fsub;
            pb0 = rowB[ni]; pb1 = rowB[ni + 1];
        }
        __syncthreads();
        consume_stage(smBase + sb, smBase + sb + OPB, wm, wn, lane, acc);
    }

#pragma unroll
    for (int mt = 0; mt < 4; mt++) {
#pragma unroll
        for (int nt = 0; nt < 4; nt++) {
            int row = m0 + wm + mt * 16 + g;
            int col = n0 + wn + nt * 8 + 2 * tg;
            float b0 = bias[col], b1 = bias[col + 1];
            float v0 = acc[mt][nt][0] + b0, v1 = acc[mt][nt][1] + b1;
            float v2 = acc[mt][nt][2] + b0, v3 = acc[mt][nt][3] + b1;
            if (ACT == 1) {
                float s0 = 1.f / (1.f + expf(-v0)), s1 = 1.f / (1.f + expf(-v1));
                float s2 = 1.f / (1.f + expf(-v2)), s3 = 1.f / (1.f + expf(-v3));
                if (col < 256) {
                    const float* h0 = g_h + (size_t)row * 256 + col;
                    const float* h1 = g_h + (size_t)(row + 8) * 256 + col;
                    ((unsigned*)g_rhb)[((size_t)row * 256 + col) >> 1] =
                        pkbf(s0 * h0[0], s1 * h0[1]);
                    ((unsigned*)g_rhb)[((size_t)(row + 8) * 256 + col) >> 1] =
                        pkbf(s2 * h1[0], s3 * h1[1]);
                } else {
                    int zc = col - 256;
                    *(float2*)(g_Z + (size_t)row * 256 + zc) = make_float2(s0, s1);
                    *(float2*)(g_Z + (size_t)(row + 8) * 256 + zc) = make_float2(s2, s3);
                }
            } else {
                float z0 = g_Z[(size_t)row * 256 + col], z1 = g_Z[(size_t)row * 256 + col + 1];
                float z2 = g_Z[(size_t)(row + 8) * 256 + col], z3 = g_Z[(size_t)(row + 8) * 256 + col + 1];
                float* hp0 = g_h + (size_t)row * 256 + col;
                float* hp1 = g_h + (size_t)(row + 8) * 256 + col;
                float n0v = (1.f - z0) * hp0[0] + z0 * tanhf(v0);
                float n1v = (1.f - z1) * hp0[1] + z1 * tanhf(v1);
                float n2v = (1.f - z2) * hp1[0] + z2 * tanhf(v2);
                float n3v = (1.f - z3) * hp1[1] + z3 * tanhf(v3);
                *(float2*)hp0 = make_float2(n0v, n1v);
                *(float2*)hp1 = make_float2(n2v, n3v);
                ((unsigned*)g_hb)[((size_t)row * 256 + col) >> 1] = pkbf(n0v, n1v);
                ((unsigned*)g_hb)[((size_t)(row + 8) * 256 + col) >> 1] = pkbf(n2v, n3v);
            }
        }
    }
}

__global__ void __launch_bounds__(256, 2) gemm_rz_k(int KT) {
    split_gemm<1>(g_hb, g_Wrzb, 768, g_brz, KT);
}
__global__ void __launch_bounds__(256, 2) gemm_hh_k(const float* __restrict__ bh, int KT) {
    split_gemm<2>(g_rhb, g_Whb, 768, bh, KT);
}

// ---------------------------------------------------------------------------
// Setup / per-step elementwise kernels
// ---------------------------------------------------------------------------
__global__ void prep_Wt(const float* __restrict__ ee) {
    size_t i = (size_t)blockIdx.x * 256 + threadIdx.x;       // 1048576
    g_Wtb[i] = f2b(ee[i]);
}
__global__ void prep_Wrz(const float* __restrict__ Wr, const float* __restrict__ Wz,
                         const float* __restrict__ br, const float* __restrict__ bz) {
    int r = blockIdx.x;   // 512
    const float* s = (r < 256) ? (Wr + (size_t)r * 768) : (Wz + (size_t)(r - 256) * 768);
    for (int c = threadIdx.x; c < 768; c += blockDim.x)
        g_Wrzb[(size_t)r * 768 + c] = f2b(s[c]);
    if (threadIdx.x == 0) g_brz[r] = (r < 256) ? br[r] : bz[r - 256];
}
__global__ void prep_Wh(const float* __restrict__ Wh) {
    size_t i = (size_t)blockIdx.x * 256 + threadIdx.x;       // 196608
    g_Whb[i] = f2b(Wh[i]);
}
__global__ void init_h(const int* __restrict__ ann_id, const float* __restrict__ te) {
    int n = blockIdx.x;
    int i = threadIdx.x;
    int id = ann_id[n];
    float a = 0.f;
    if (i < 64 && id > 0) a = te[(size_t)(id - 1) * 64 + i];
    if (i < 64) g_ann[(size_t)n * 64 + i] = a;
    float v = (i < 64) ? a : 0.f;
    g_h[(size_t)n * 256 + i] = v;
    g_hb[(size_t)n * 256 + i] = f2b(v);
}
__global__ void prep_AG() {
    size_t i = (size_t)blockIdx.x * 256 + threadIdx.x;       // 2097152 float4
    ((float4*)g_AG)[i] = make_float4(0.f, 0.f, 0.f, 0.f);
}
__global__ void conv_AG() {
    size_t i = (size_t)blockIdx.x * 256 + threadIdx.x;       // 2097152 float4
    float4 v = ((const float4*)g_AG)[i];
    ((uint2*)g_AGb)[i] = make_uint2(pkbf(v.x, v.y), pkbf(v.z, v.w));
}

// ---------------------------------------------------------------------------
// Readout
// ---------------------------------------------------------------------------
__global__ void readout_k(const float* __restrict__ Wa, const float* __restrict__ ba,
                          const float* __restrict__ Wo, const float* __restrict__ bo) {
    int warp = (blockIdx.x * blockDim.x + threadIdx.x) >> 5;
    int lane = threadIdx.x & 31;
    const float* hrow = g_h + (size_t)warp * 256;
    const float* arow = g_ann + (size_t)warp * 64;
    float sa = 0.f, so = 0.f;
#pragma unroll
    for (int k = lane; k < 320; k += 32) {
        float v = (k < 256) ? hrow[k] : arow[k - 256];
        sa += v * Wa[k];
        so += v * Wo[k];
    }
#pragma unroll
    for (int off = 16; off; off >>= 1) {
        sa += __shfl_xor_sync(0xffffffffu, sa, off);
        so += __shfl_xor_sync(0xffffffffu, so, off);
    }
    if (lane == 0) {
        float atten = 1.f / (1.f + expf(-(sa + ba[0])));
        float ou = tanhf(so + bo[0]);
        g_nodeval[warp] = atten * ou;
    }
}
__global__ void finalize_k(float* __restrict__ out) {
    __shared__ float sh[256];
    int b = blockIdx.x;
    float s = 0.f;
    for (int i = threadIdx.x; i < Nn; i += 256) s += g_nodeval[(size_t)b * Nn + i];
    sh[threadIdx.x] = s;
    __syncthreads();
    for (int k = 128; k; k >>= 1) {
        if (threadIdx.x < k) sh[threadIdx.x] += sh[threadIdx.x + k];
        __syncthreads();
    }
    if (threadIdx.x == 0) out[b] = 1.f / (1.f + expf(-sh[0]));
}

// ---------------------------------------------------------------------------
// Launch
// ---------------------------------------------------------------------------
extern "C" void kernel_launch(void* const* d_in, const int* in_sizes, int n_in,
                              void* d_out, int out_size) {
    (void)in_sizes; (void)n_in; (void)out_size;
    const int* ann_id = (const int*)d_in[0];
    const int* src    = (const int*)d_in[1];
    const int* dst    = (const int*)d_in[2];
    const int* et     = (const int*)d_in[3];
    const float* ee   = (const float*)d_in[4];
    const float* eb   = (const float*)d_in[5];
    const float* te   = (const float*)d_in[6];
    const float* Wr   = (const float*)d_in[7];
    const float* br   = (const float*)d_in[8];
    const float* Wz   = (const float*)d_in[9];
    const float* bz   = (const float*)d_in[10];
    const float* Wh   = (const float*)d_in[11];
    const float* bh   = (const float*)d_in[12];
    const float* Wa   = (const float*)d_in[13];
    const float* ba   = (const float*)d_in[14];
    const float* Wo   = (const float*)d_in[15];
    const float* bo   = (const float*)d_in[16];
    float* out = (float*)d_out;

    cudaFuncSetAttribute(gather_gemm_k, cudaFuncAttributeMaxDynamicSharedMemorySize, SMEM_BYTES);
    cudaFuncSetAttribute(gemm_rz_k, cudaFuncAttributeMaxDynamicSharedMemorySize, SMEM_BYTES);
    cudaFuncSetAttribute(gemm_hh_k, cudaFuncAttributeMaxDynamicSharedMemorySize, SMEM_BYTES);

    prep_Wt<<<4096, 256>>>(ee);
    prep_Wrz<<<512, 256>>>(Wr, Wz, br, bz);
    prep_Wh<<<768, 256>>>(Wh);
    init_h<<<Bn * Nn, 256>>>(ann_id, te);

    zero_sort_k<<<1, 32>>>();
    hist_k<<<256, 256>>>(et);
    scan_k<<<1, 32>>>();
    build_k<<<256, 256>>>(et);

    for (int step = 0; step < 3; step++) {
        prep_AG<<<8192, 256>>>();
        // step 0: h has only 64 nonzero cols -> gather K=64; gate region2 trims to 2 tiles
        gather_gemm_k<<<dim3(544, 2, 2), 256, SMEM_BYTES>>>(src, dst, eb,
                                                            step == 0 ? 2 : 8);
        conv_AG<<<8192, 256>>>();
        gemm_rz_k<<<dim3(128, 4, 1), 256, SMEM_BYTES>>>(step == 0 ? 18 : 24);
        gemm_hh_k<<<dim3(128, 2, 1), 256, SMEM_BYTES>>>(bh, step == 0 ? 18 : 24);
    }

    readout_k<<<2048, 256>>>(Wa, ba, Wo, bo);
    finalize_k<<<4, 256>>>(out);
}